// round 16
// baseline (speedup 1.0000x reference)
#include <cuda_runtime.h>
#include <cuda_fp16.h>
#include <cstdint>

#define Bsz   2048
#define Lseq  256

// ---------------- device scratch ----------------
__device__ float g_T0[2 * 128 * 256];                 // token table [dir][tok][cell][gate4] fp32
__device__ __half g_y0[(size_t)Lseq * Bsz * 128];     // layer-0 output fp16 [t][b][128]
__device__ float g_hfin[Bsz * 128];                   // layer-1 final hidden [b][hf|hb]

// ---------------- helpers ----------------
__device__ __forceinline__ uint32_t s2u(const void* p) {
    uint32_t a;
    asm("{ .reg .u64 t; cvta.to.shared.u64 t, %1; cvt.u32.u64 %0, t; }" : "=r"(a) : "l"(p));
    return a;
}
__device__ __forceinline__ float tanha(float x) {
    float y; asm("tanh.approx.f32 %0, %1;" : "=f"(y) : "f"(x)); return y;
}
__device__ __forceinline__ float sigf(float x) { return fmaf(0.5f, tanha(0.5f * x), 0.5f); }

__device__ __forceinline__ void ldsm4(uint32_t* r, uint32_t addr) {
    asm volatile("ldmatrix.sync.aligned.m8n8.x4.shared.b16 {%0,%1,%2,%3}, [%4];"
        : "=r"(r[0]), "=r"(r[1]), "=r"(r[2]), "=r"(r[3]) : "r"(addr));
}
__device__ __forceinline__ void mmaf16(float* d, const uint32_t* a, const uint32_t* b) {
    asm volatile("mma.sync.aligned.m16n8k16.row.col.f32.f16.f16.f32 "
        "{%0,%1,%2,%3}, {%4,%5,%6,%7}, {%8,%9}, {%0,%1,%2,%3};"
        : "+f"(d[0]), "+f"(d[1]), "+f"(d[2]), "+f"(d[3])
        : "r"(a[0]), "r"(a[1]), "r"(a[2]), "r"(a[3]), "r"(b[0]), "r"(b[1]));
}
__device__ __forceinline__ void split2h(float v, __half& hi, __half& lo) {
    hi = __float2half_rn(v);
    lo = __float2half_rn(v - __half2float(hi));
}

// ================= kernel 1: layer-0 token table (fp32 exact) =================
__global__ void table_kernel(const float* __restrict__ emb,
                             const float* __restrict__ Wih0,
                             const float* __restrict__ b0) {
    const int v = blockIdx.x, dir = blockIdx.y, tid = threadIdx.x;
    const int cell = tid >> 2, gate = tid & 3;
    __shared__ float se[64];
    if (tid < 64) se[tid] = emb[v * 64 + tid];
    __syncthreads();
    const float* wrow = Wih0 + (size_t)(dir * 256 + gate * 64 + cell) * 64;
    float s = b0[dir * 512 + gate * 64 + cell] + b0[dir * 512 + 256 + gate * 64 + cell];
#pragma unroll
    for (int k = 0; k < 64; k++) s += se[k] * wrow[k];
    g_T0[((size_t)(dir * 128 + v) * 64 + cell) * 4 + gate] = s;
}

// ================= kernel 2: layer-0 LSTM (unchanged; proven r13-r15) =================
__global__ void __launch_bounds__(256, 2)
lstm0_kernel(const int* __restrict__ xtok, const float* __restrict__ Whh0) {
    constexpr int SA  = 144;
    constexpr int ALO = 256 * SA;
    constexpr int BH0 = 2 * 256 * SA;
    constexpr int BH1 = BH0 + 16 * SA;
    extern __shared__ __align__(16) char smem[];
    const uint32_t sb = s2u(smem);
    const int dir = blockIdx.y, b0i = blockIdx.x * 16;
    const int tid = threadIdx.x, lane = tid & 31, w = tid >> 5;

    {
        const int m = tid;
        const int cellm = 8 * (m >> 5) + (m & 7), gate = (m >> 3) & 3;
        const float* sh = Whh0 + (size_t)(dir * 256 + gate * 64 + cellm) * 64;
        char* rowp = smem + m * SA;
#pragma unroll 8
        for (int k = 0; k < 64; k++) {
            __half hi, lo; split2h(sh[k], hi, lo);
            *(__half*)(rowp + k * 2) = hi;
            *(__half*)(rowp + ALO + k * 2) = lo;
        }
    }
    if (tid < 128) {
        int row = tid >> 3, ch = tid & 7;
        *(uint4*)(smem + BH0 + row * SA + ch * 16) = make_uint4(0, 0, 0, 0);
    }
    __syncthreads();

    const int lrow = ((lane >> 3) & 1) * 8 + (lane & 7);
    const int lk8 = lane >> 4;
    const uint32_t a_base = sb + (32 * w + lrow) * SA + lk8 * 16;
    const uint32_t alo_base = a_base + ALO;
    uint32_t ahi0[4][4], ahi1[4][4];
#pragma unroll
    for (int kt = 0; kt < 4; kt++) {
        ldsm4(ahi0[kt], a_base + kt * 32);
        ldsm4(ahi1[kt], a_base + 16 * SA + kt * 32);
    }
    const int bn = 8 * (lane >> 4) + (lane & 7), bk8 = (lane >> 3) & 1;
    const uint32_t bh_base0 = sb + BH0 + bn * SA + bk8 * 16;
    const uint32_t bh_base1 = sb + BH1 + bn * SA + bk8 * 16;

    const int cell = 8 * w + (lane >> 2);
    float cs[2][2];
    cs[0][0] = cs[0][1] = cs[1][0] = cs[1][1] = 0.f;
    const int srow = (tid >> 3) & 15, sch = tid & 7;
    const float* T0 = g_T0 + (size_t)dir * 128 * 256;

    for (int t = 0; t < Lseq; t++) {
        const int tcur = dir ? (Lseq - 1 - t) : t;
        const uint32_t bh_cur = (t & 1) ? bh_base1 : bh_base0;
        const uint32_t bwofs  = (t & 1) ? BH0 : BH1;

        if (t > 0 && tid < 128) {
            int tprev = dir ? (Lseq - t) : (t - 1);
            uint32_t rofs = ((t & 1) ? BH1 : BH0) + srow * SA + sch * 16;
            *(uint4*)(g_y0 + ((size_t)tprev * Bsz + b0i + srow) * 128 + dir * 64 + sch * 8)
                = *(uint4*)(smem + rofs);
        }

        float4 tv[2][2];
#pragma unroll
        for (int nt = 0; nt < 2; nt++)
#pragma unroll
            for (int hh = 0; hh < 2; hh++) {
                int bb = 8 * nt + 2 * (lane & 3) + hh;
                int tok = __ldg(&xtok[(b0i + bb) * Lseq + tcur]);
                tv[nt][hh] = *(const float4*)(T0 + ((size_t)tok * 64 + cell) * 4);
            }

        float acc[2][2][4];
#pragma unroll
        for (int mt = 0; mt < 2; mt++)
#pragma unroll
            for (int nt = 0; nt < 2; nt++)
#pragma unroll
                for (int r = 0; r < 4; r++) acc[mt][nt][r] = 0.f;
#pragma unroll
        for (int kt = 0; kt < 4; kt++) {
            uint32_t alo0[4], alo1[4], bh0[4];
            ldsm4(alo0, alo_base + kt * 32);
            ldsm4(alo1, alo_base + 16 * SA + kt * 32);
            ldsm4(bh0, bh_cur + kt * 32);
            mmaf16(acc[0][0], ahi0[kt], bh0);     mmaf16(acc[0][0], alo0, bh0);
            mmaf16(acc[0][1], ahi0[kt], bh0 + 2); mmaf16(acc[0][1], alo0, bh0 + 2);
            mmaf16(acc[1][0], ahi1[kt], bh0);     mmaf16(acc[1][0], alo1, bh0);
            mmaf16(acc[1][1], ahi1[kt], bh0 + 2); mmaf16(acc[1][1], alo1, bh0 + 2);
        }

#pragma unroll
        for (int nt = 0; nt < 2; nt++)
#pragma unroll
            for (int hh = 0; hh < 2; hh++) {
                float iv = acc[0][nt][hh]     + tv[nt][hh].x;
                float fv = acc[0][nt][2 + hh] + tv[nt][hh].y;
                float gv = acc[1][nt][hh]     + tv[nt][hh].z;
                float ov = acc[1][nt][2 + hh] + tv[nt][hh].w;
                float c = sigf(fv) * cs[nt][hh] + sigf(iv) * tanha(gv);
                cs[nt][hh] = c;
                float h = sigf(ov) * tanha(c);
                int bb = 8 * nt + 2 * (lane & 3) + hh;
                *(__half*)(smem + bwofs + bb * SA + cell * 2) = __float2half_rn(h);
            }
        __syncthreads();
    }
    if (tid < 128) {
        int tprev = dir ? 0 : (Lseq - 1);
        *(uint4*)(g_y0 + ((size_t)tprev * Bsz + b0i + srow) * 128 + dir * 64 + sch * 8)
            = *(uint4*)(smem + BH0 + srow * SA + sch * 16);
    }
}

// ================= kernel 3: layer-1 LSTM =================
// NB=16, 2 CTAs/SM via smem overlay: x-weights loaded to registers in the
// prologue, then their smem region is reused for the x/h data buffers.
// h-weights stay resident (per-step LDSM). Weights fp16 hi-only.
__global__ void __launch_bounds__(256, 2)
lstm1_kernel(const float* __restrict__ Wih1, const float* __restrict__ Whh1,
             const float* __restrict__ bias) {
    constexpr int SH  = 144;                  // h row stride
    constexpr int SX  = 272;                  // x row stride
    constexpr int HW  = 0;                    // h-weights [256][SH], persistent  36864
    constexpr int XW  = 256 * SH;             // x-weights [256][SX], prologue    36864..106496
    constexpr int BX0 = XW;                   // overlay after prologue
    constexpr int BX1 = BX0 + 16 * SX;        // +4352
    constexpr int BH0 = BX1 + 16 * SX;        // +4352
    constexpr int BH1 = BH0 + 16 * SH;        // +2304 (overlay end 48384 < 106496)

    extern __shared__ __align__(16) char smem[];
    const uint32_t sb = s2u(smem);
    const int dir = blockIdx.y, b0i = blockIdx.x * 16;
    const int tid = threadIdx.x, lane = tid & 31, w = tid >> 5;

    // fill weights (hi only), permuted rows: x into XW, h into HW
    {
        const int m = tid;
        const int cellm = 8 * (m >> 5) + (m & 7), gate = (m >> 3) & 3;
        const int grow = dir * 256 + gate * 64 + cellm;
        const float* si = Wih1 + (size_t)grow * 128;
        const float* sh = Whh1 + (size_t)grow * 64;
        char* xrow = smem + XW + m * SX;
        for (int k = 0; k < 128; k++)
            *(__half*)(xrow + k * 2) = __float2half_rn(si[k]);
        char* hrow = smem + HW + m * SH;
#pragma unroll 8
        for (int k = 0; k < 64; k++)
            *(__half*)(hrow + k * 2) = __float2half_rn(sh[k]);
    }
    __syncthreads();

    // x-A fragments -> registers (8 kt covering K=128)
    const int lrow = ((lane >> 3) & 1) * 8 + (lane & 7);
    const int lk8  = lane >> 4;
    const uint32_t ax_base = sb + XW + (32 * w + lrow) * SX + lk8 * 16;
    uint32_t axh0[8][4], axh1[8][4];
#pragma unroll
    for (int kt = 0; kt < 8; kt++) {
        ldsm4(axh0[kt], ax_base + kt * 32);
        ldsm4(axh1[kt], ax_base + 16 * SX + kt * 32);
    }
    const uint32_t ah_base = sb + HW + (32 * w + lrow) * SH + lk8 * 16;
    __syncthreads();   // all XW reads done; region now reusable as buffers

    // zero h buffer 0 + stage x(0) -> BX0, x(1) -> BX1
    if (tid < 128) {
        int row = tid >> 3, ch = tid & 7;
        *(uint4*)(smem + BH0 + row * SH + ch * 16) = make_uint4(0, 0, 0, 0);
    }
    const int r0 = tid >> 4, c0 = tid & 15;   // 16 rows x 16 chunks
    {
        int t0n = dir ? (Lseq - 1) : 0;
        int t1n = dir ? (Lseq - 2) : 1;
        *(uint4*)(smem + BX0 + r0 * SX + c0 * 16)
            = *(const uint4*)(g_y0 + ((size_t)t0n * Bsz + b0i + r0) * 128 + c0 * 8);
        *(uint4*)(smem + BX1 + r0 * SX + c0 * 16)
            = *(const uint4*)(g_y0 + ((size_t)t1n * Bsz + b0i + r0) * 128 + c0 * 8);
    }
    __syncthreads();

    const int bn  = 8 * (lane >> 4) + (lane & 7);
    const int bk8 = (lane >> 3) & 1;
    const uint32_t bxf0 = sb + BX0 + bn * SX + bk8 * 16;
    const uint32_t bxf1 = sb + BX1 + bn * SX + bk8 * 16;
    const uint32_t bhf0 = sb + BH0 + bn * SH + bk8 * 16;
    const uint32_t bhf1 = sb + BH1 + bn * SH + bk8 * 16;

    const int cell = 8 * w + (lane >> 2);
    const float* bp = bias + dir * 512;
    const float bi_ = bp[cell]       + bp[256 + cell];
    const float bf_ = bp[64 + cell]  + bp[320 + cell];
    const float bg_ = bp[128 + cell] + bp[384 + cell];
    const float bo_ = bp[192 + cell] + bp[448 + cell];

    float cs[2][2];
    cs[0][0] = cs[0][1] = cs[1][0] = cs[1][1] = 0.f;

    for (int t = 0; t < Lseq; t++) {
        const uint32_t bx_cur = (t & 1) ? bxf1 : bxf0;
        const uint32_t bh_cur = (t & 1) ? bhf1 : bhf0;
        const uint32_t bhw    = (t & 1) ? BH0 : BH1;
        const uint32_t bxw    = (t & 1) ? BX0 : BX1;

        // prefetch x(t+1) into registers (overlaps mma)
        uint4 pf0;
        if (t + 1 < Lseq) {
            int tn = dir ? (Lseq - 2 - t) : (t + 1);
            pf0 = *(const uint4*)(g_y0 + ((size_t)tn * Bsz + b0i + r0) * 128 + c0 * 8);
        }

        float acc[2][2][4];
#pragma unroll
        for (int mt = 0; mt < 2; mt++)
#pragma unroll
            for (int nt = 0; nt < 2; nt++)
#pragma unroll
                for (int r = 0; r < 4; r++) acc[mt][nt][r] = 0.f;

        // x-part (A frags in registers)
#pragma unroll
        for (int kt = 0; kt < 8; kt++) {
            uint32_t bx0[4];
            ldsm4(bx0, bx_cur + kt * 32);
            mmaf16(acc[0][0], axh0[kt], bx0);
            mmaf16(acc[0][1], axh0[kt], bx0 + 2);
            mmaf16(acc[1][0], axh1[kt], bx0);
            mmaf16(acc[1][1], axh1[kt], bx0 + 2);
        }
        // h-part (A via LDSM from resident h-weight region)
#pragma unroll
        for (int kh = 0; kh < 4; kh++) {
            uint32_t ah0[4], ah1[4], bh0[4];
            ldsm4(ah0, ah_base + kh * 32);
            ldsm4(ah1, ah_base + 16 * SH + kh * 32);
            ldsm4(bh0, bh_cur + kh * 32);
            mmaf16(acc[0][0], ah0, bh0);
            mmaf16(acc[0][1], ah0, bh0 + 2);
            mmaf16(acc[1][0], ah1, bh0);
            mmaf16(acc[1][1], ah1, bh0 + 2);
        }

        // epilogue -> OTHER h buffer
#pragma unroll
        for (int nt = 0; nt < 2; nt++)
#pragma unroll
            for (int hh = 0; hh < 2; hh++) {
                int bb = 8 * nt + 2 * (lane & 3) + hh;
                float iv = acc[0][nt][hh]     + bi_;
                float fv = acc[0][nt][2 + hh] + bf_;
                float gv = acc[1][nt][hh]     + bg_;
                float ov = acc[1][nt][2 + hh] + bo_;
                float c = sigf(fv) * cs[nt][hh] + sigf(iv) * tanha(gv);
                cs[nt][hh] = c;
                float h = sigf(ov) * tanha(c);
                *(__half*)(smem + bhw + bb * SH + cell * 2) = __float2half_rn(h);
                if (t == Lseq - 1)
                    g_hfin[(b0i + bb) * 128 + dir * 64 + cell] = h;
            }

        // store prefetched x(t+1) -> OTHER x buffer
        if (t + 1 < Lseq)
            *(uint4*)(smem + bxw + r0 * SX + c0 * 16) = pf0;
        __syncthreads();   // h(t) + x(t+1) visible for next step
    }
}

// ================= kernel 4: MLP head =================
__global__ void __launch_bounds__(256)
head_kernel(const float* __restrict__ W1, const float* __restrict__ bf1,
            const float* __restrict__ W2, const float* __restrict__ bf2,
            float* __restrict__ out) {
    extern __shared__ float hs[];
    float* sW1 = hs;                           // [64][129]
    float* sh  = hs + 64 * 129;                // [32][129]
    float* sW2 = hs + 64 * 129 + 32 * 129;     // [64]
    float* sb1 = sW2 + 64;                     // [64]
    const int tid = threadIdx.x;
    const int b0 = blockIdx.x * 32;

    for (int i = tid; i < 64 * 128; i += 256) sW1[(i >> 7) * 129 + (i & 127)] = W1[i];
    for (int i = tid; i < 32 * 128; i += 256) sh[(i >> 7) * 129 + (i & 127)] = g_hfin[b0 * 128 + i];
    if (tid < 64) { sW2[tid] = W2[tid]; sb1[tid] = bf1[tid]; }
    __syncthreads();

    const int bi = tid >> 3, g8 = tid & 7;
    const float* hrow = sh + bi * 129;
    float part = 0.f;
#pragma unroll
    for (int jj = 0; jj < 8; jj++) {
        int j = g8 * 8 + jj;
        float z = sb1[j];
        const float* wrow = sW1 + j * 129;
#pragma unroll 16
        for (int k = 0; k < 128; k++) z += hrow[k] * wrow[k];
        part += fmaxf(z, 0.f) * sW2[j];
    }
#pragma unroll
    for (int o = 4; o; o >>= 1) part += __shfl_down_sync(0xffffffffu, part, o, 8);
    if (g8 == 0) out[b0 + bi] = part + bf2[0];
}

// ================= launch =================
extern "C" void kernel_launch(void* const* d_in, const int* in_sizes, int n_in,
                              void* d_out, int out_size) {
    const int*   x    = (const int*)  d_in[0];
    const float* emb  = (const float*)d_in[1];
    const float* Wih0 = (const float*)d_in[2];
    const float* Whh0 = (const float*)d_in[3];
    const float* b0   = (const float*)d_in[4];
    const float* Wih1 = (const float*)d_in[5];
    const float* Whh1 = (const float*)d_in[6];
    const float* b1   = (const float*)d_in[7];
    const float* W1   = (const float*)d_in[8];
    const float* bf1  = (const float*)d_in[9];
    const float* W2   = (const float*)d_in[10];
    const float* bf2  = (const float*)d_in[11];
    float* out = (float*)d_out;

    const int SM0 = 2 * 256 * 144 + 2 * 16 * 144;     // 78336
    const int SM1 = 256 * 144 + 256 * 272;            // 106496 (x-weight region overlaid by buffers)
    const int SMH = (64 * 129 + 32 * 129 + 128) * 4;
    cudaFuncSetAttribute(lstm0_kernel, cudaFuncAttributeMaxDynamicSharedMemorySize, SM0);
    cudaFuncSetAttribute(lstm1_kernel, cudaFuncAttributeMaxDynamicSharedMemorySize, SM1);
    cudaFuncSetAttribute(head_kernel,  cudaFuncAttributeMaxDynamicSharedMemorySize, SMH);

    table_kernel<<<dim3(128, 2), 256>>>(emb, Wih0, b0);
    lstm0_kernel<<<dim3(Bsz / 16, 2), 256, SM0>>>(x, Whh0);
    lstm1_kernel<<<dim3(Bsz / 16, 2), 256, SM1>>>(Wih1, Whh1, b1);
    head_kernel<<<64, 256, SMH>>>(W1, bf1, W2, bf2, out);
}